// round 15
// baseline (speedup 1.0000x reference)
#include <cuda_runtime.h>
#include <cuda_fp16.h>
#include <cstdint>

// Problem constants
#define BB 16
#define CC 64
#define HH 256
#define WW 256
#define GG 8
#define GS 8

// ---------------- k1 tiling ----------------
// A tile: 4 dy-rows x 136 px-rows x 144B (72 halfs: 64ci + pad) = 78336 B
//   (px-row index = gw - (w0-4); ldsm uses idx = p + 3; rows 0-2/133-135 unused)
// B: per-tap [64co][64ci] fp16 swizzled, double buffer 2 x 8192
// scratch: fp32 conversion bounce, 2 x [16ci][136px] = 2 x 8704 B
#define A_STRIDE 144
#define A_BYTES (4 * 136 * A_STRIDE)        // 78336
#define B_OFF A_BYTES
#define B_TAP 8192
#define SCR_OFF (B_OFF + 2 * B_TAP)         // 94720
#define SCR_CHUNK 8704                       // 16*136*4
#define SMEM1 (SCR_OFF + 2 * SCR_CHUNK)     // 112128 -> 2 CTAs/SM
#define EPI_PAD 68

// Big device buffers (bss, not allocations)
__device__ float g_xconv[(size_t)BB * HH * WW * CC];   // [b][h][w][c]
__device__ __align__(16) __half g_wsw[9][CC * CC];     // w fp16 [tap][co][ci] swizzled

__device__ __forceinline__ uint32_t smem_u32(const void* p) {
    uint32_t a;
    asm("{ .reg .u64 t; cvta.to.shared.u64 t, %1; cvt.u32.u64 %0, t; }" : "=r"(a) : "l"(p));
    return a;
}
__device__ __forceinline__ void ldsm4(uint32_t* r, uint32_t addr) {
    asm volatile("ldmatrix.sync.aligned.m8n8.x4.shared.b16 {%0,%1,%2,%3}, [%4];"
                 : "=r"(r[0]), "=r"(r[1]), "=r"(r[2]), "=r"(r[3]) : "r"(addr));
}
__device__ __forceinline__ void hmma(float* c, const uint32_t* a, const uint32_t* b) {
    asm volatile(
        "mma.sync.aligned.m16n8k16.row.col.f32.f16.f16.f32 "
        "{%0,%1,%2,%3}, {%4,%5,%6,%7}, {%8,%9}, {%0,%1,%2,%3};"
        : "+f"(c[0]), "+f"(c[1]), "+f"(c[2]), "+f"(c[3])
        : "r"(a[0]), "r"(a[1]), "r"(a[2]), "r"(a[3]), "r"(b[0]), "r"(b[1]));
}
__device__ __forceinline__ void cpa16(uint32_t dst, const void* src, int szbytes) {
    asm volatile("cp.async.ca.shared.global [%0], [%1], 16, %2;"
                 :: "r"(dst), "l"(src), "r"(szbytes) : "memory");
}
#define CPA_COMMIT() asm volatile("cp.async.commit_group;" ::: "memory")
#define CPA_WAIT0()  asm volatile("cp.async.wait_group 0;" ::: "memory")
#define CPA_WAIT1()  asm volatile("cp.async.wait_group 1;" ::: "memory")

// ---------------------------------------------------------------------------
// k0w: weights -> fp16, layout [tap][co][ci] with 16B-chunk swizzle
// ---------------------------------------------------------------------------
extern "C" __global__ void k0_wconv(const float* __restrict__ w)
{
    int tap = blockIdx.x;
    for (int i = threadIdx.x; i < CC * CC; i += 256) {
        int co = i >> 6, ci = i & 63;
        float v = w[(size_t)(co * CC + ci) * 9 + tap];
        uint32_t byte = (uint32_t)co * 128 + ((((uint32_t)ci >> 3) ^ ((uint32_t)co & 7)) << 4)
                      + ((uint32_t)ci & 7) * 2;
        g_wsw[tap][byte >> 1] = __float2half(v);
    }
}

// ---------------------------------------------------------------------------
// k1: conv3x3 + bias via mma.sync fp16, inline fp32->fp16 A conversion.
//   Prologue: 16 chunks (4 rows x 4 ci-groups) cp.async fp32 -> scratch,
//   vectorized convert -> A tile (144B px rows, no swizzle needed).
//   Mainloop: 9 tap-passes, B streamed double-buffered. out [b][h][w][c].
//   grid (2, 128, 16); 256 threads; 2 CTAs/SM
// ---------------------------------------------------------------------------
extern "C" __global__ void __launch_bounds__(256, 2)
k1_conv(const float* __restrict__ x,
        const float* __restrict__ cb)
{
    extern __shared__ char smem[];
    const uint32_t sA = smem_u32(smem);
    const int tid = threadIdx.x;
    const int wid = tid >> 5;
    const int lid = tid & 31;

    const int b  = blockIdx.z;
    const int h0 = blockIdx.y * 2;
    const int w0 = blockIdx.x * 128;

    const int am  = lid & 15;
    const int akh = (lid >> 4) & 1;
    const int bco = (lid & 7) + ((lid >= 16) ? 8 : 0);
    const int bkh = (lid >> 3) & 1;
    const int pbase = wid * 16;

    // ---- staging lambdas ----
    auto stage_chunk = [&](int cidx, int buf) {
        int dy = cidx >> 2, cg = cidx & 3;
        int gh = h0 - 1 + dy;
        bool rowok = ((unsigned)gh < (unsigned)HH);
        const float* base = x + (((size_t)b * CC + cg * 16) * HH + gh) * WW + (w0 - 4);
        uint32_t sdst = sA + SCR_OFF + buf * SCR_CHUNK;
        for (int i = tid; i < 544; i += 256) {          // 16 ci x 34 blocks
            int ci  = i / 34;
            int blk = i - ci * 34;
            bool ok = rowok && !(blk == 0 && w0 == 0) && !(blk == 33 && w0 == 128);
            cpa16(sdst + (uint32_t)(ci * 544 + blk * 16),
                  base + (size_t)ci * HH * WW + blk * 4, ok ? 16 : 0);
        }
    };
    auto convert_chunk = [&](int cidx, int buf) {
        int dy = cidx >> 2, cg = cidx & 3;
        const float* scr = (const float*)(smem + SCR_OFF + buf * SCR_CHUNK);
        for (int i = tid; i < 136; i += 256) {          // 4 ci4-groups x 34 px4
            int ci4 = i / 34;
            int px4 = i - ci4 * 34;
            float4 q0 = *(const float4*)(scr + (ci4 * 4 + 0) * 136 + px4 * 4);
            float4 q1 = *(const float4*)(scr + (ci4 * 4 + 1) * 136 + px4 * 4);
            float4 q2 = *(const float4*)(scr + (ci4 * 4 + 2) * 136 + px4 * 4);
            float4 q3 = *(const float4*)(scr + (ci4 * 4 + 3) * 136 + px4 * 4);
            const float* f0 = (const float*)&q0;
            const float* f1 = (const float*)&q1;
            const float* f2 = (const float*)&q2;
            const float* f3 = (const float*)&q3;
            char* arow = smem + (dy * 136 + px4 * 4) * A_STRIDE + cg * 32 + ci4 * 8;
#pragma unroll
            for (int k = 0; k < 4; k++) {
                __half2 lo = __floats2half2_rn(f0[k], f1[k]);
                __half2 hi = __floats2half2_rn(f2[k], f3[k]);
                uint2 v;
                v.x = *(uint32_t*)&lo;
                v.y = *(uint32_t*)&hi;
                *(uint2*)(arow + k * A_STRIDE) = v;
            }
        }
    };
    auto stageB = [&](int buf, int tap) {
        uint32_t dst = sA + B_OFF + buf * B_TAP;
        const char* s0 = (const char*)&g_wsw[tap][0];
        for (int i = tid; i < B_TAP / 16; i += 256)
            cpa16(dst + i * 16, s0 + i * 16, 16);
    };

    float c[2][8][4];
#pragma unroll
    for (int hh = 0; hh < 2; hh++)
#pragma unroll
        for (int nb = 0; nb < 8; nb++)
#pragma unroll
            for (int q = 0; q < 4; q++) c[hh][nb][q] = 0.f;

    // ---- prologue: B(tap0) + pipelined A conversion ----
    stageB(0, 0);
    stage_chunk(0, 0);
    CPA_COMMIT();
    for (int cidx = 0; cidx < 16; cidx++) {
        int buf = cidx & 1;
        if (cidx < 15) {
            stage_chunk(cidx + 1, buf ^ 1);
            CPA_COMMIT();
            CPA_WAIT1();          // chunk cidx complete; cidx+1 may be in flight
        } else {
            CPA_WAIT0();
        }
        __syncthreads();
        convert_chunk(cidx, buf);
    }
    __syncthreads();              // A tile fully written

    // ---- mainloop: 9 tap-passes ----
    int cur = 0;
    for (int tap = 0; tap < 9; tap++) {
        CPA_WAIT0();
        __syncthreads();

        if (tap < 8) {
            stageB(cur ^ 1, tap + 1);
            CPA_COMMIT();
        }

        const int dy = tap / 3, dx = tap - 3 * (tap / 3);
        const uint32_t sBc = sA + B_OFF + cur * B_TAP + bco * 128;

#pragma unroll
        for (int kb = 0; kb < 4; kb++) {
            uint32_t a[2][4];
#pragma unroll
            for (int hh = 0; hh < 2; hh++) {
                int row = (hh + dy) * 136 + pbase + dx + am + 3;
                uint32_t addr = sA + (uint32_t)row * A_STRIDE + (uint32_t)(kb * 2 + akh) * 16;
                ldsm4(a[hh], addr);
            }
            uint32_t bbf[4][4];
#pragma unroll
            for (int j = 0; j < 4; j++) {
                uint32_t co = (uint32_t)(j * 16 + bco);
                uint32_t addr = sBc + j * 16 * 128
                              + ((((uint32_t)(kb * 2 + bkh)) ^ (co & 7)) << 4);
                ldsm4(bbf[j], addr);
            }
#pragma unroll
            for (int hh = 0; hh < 2; hh++)
#pragma unroll
                for (int j = 0; j < 4; j++) {
                    hmma(c[hh][2 * j + 0], a[hh], &bbf[j][0]);
                    hmma(c[hh][2 * j + 1], a[hh], &bbf[j][2]);
                }
        }
        cur ^= 1;
    }

    // ---- epilogue: frags -> smem [256 px][68] f32 -> coalesced gmem ----
    __syncthreads();
    float* smf = (float*)smem;
    const int mrow = (lid >> 2);
    const int qcol = (lid & 3) * 2;
#pragma unroll
    for (int hh = 0; hh < 2; hh++)
#pragma unroll
        for (int nb = 0; nb < 8; nb++) {
            int m0 = hh * 128 + pbase + mrow;
            int co = nb * 8 + qcol;
            *(float2*)&smf[m0 * EPI_PAD + co]       = make_float2(c[hh][nb][0], c[hh][nb][1]);
            *(float2*)&smf[(m0 + 8) * EPI_PAD + co] = make_float2(c[hh][nb][2], c[hh][nb][3]);
        }
    __syncthreads();

    for (int i = tid; i < 256 * 16; i += 256) {
        int pix = i >> 4, k4 = i & 15;
        float4 v = *(float4*)&smf[pix * EPI_PAD + k4 * 4];
        int cc4 = k4 * 4;
        v.x += __ldg(cb + cc4 + 0);
        v.y += __ldg(cb + cc4 + 1);
        v.z += __ldg(cb + cc4 + 2);
        v.w += __ldg(cb + cc4 + 3);
        int gh = h0 + (pix >> 7);
        int gw = w0 + (pix & 127);
        *(float4*)(g_xconv + (((size_t)b * HH + gh) * WW + gw) * CC + cc4) = v;
    }
}

// ---------------------------------------------------------------------------
// k2: fused epilogue, channels-last smem tile [pix][68] (unchanged R14)
// ---------------------------------------------------------------------------
#define TW 32
#define TH 8
#define HALO_W (TW + 2)
#define HALO_H (TH + 2)
#define K2_PIX (HALO_W * HALO_H)           // 340
#define K2_PAD 68
#define K2_XS_FLOATS (K2_PIX * K2_PAD)
#define K2_WD_OFF K2_XS_FLOATS
#define K2_CB_OFF (K2_WD_OFF + 576)
#define K2_GS_OFF (K2_CB_OFF + CC)
#define K2_GB_OFF (K2_GS_OFF + CC)
#define K2_SMEM_FLOATS (K2_GB_OFF + CC)
#define K2_SMEM_BYTES (K2_SMEM_FLOATS * 4)

extern "C" __global__ void __launch_bounds__(256, 2)
k2_fused(const float* __restrict__ w,
         const float* __restrict__ cb,
         const float* __restrict__ gscale,
         const float* __restrict__ gbias,
         float* __restrict__ out)
{
    extern __shared__ float smemf[];
    float* xs  = smemf;
    float* wd4 = smemf + K2_WD_OFF;
    float* cbs = smemf + K2_CB_OFF;
    float* gss = smemf + K2_GS_OFF;
    float* gbs = smemf + K2_GB_OFF;

    const uint32_t sXS = smem_u32(xs);
    const int tid = threadIdx.x;
    const int b  = blockIdx.z;
    const int h0 = blockIdx.y * TH;
    const int w0 = blockIdx.x * TW;

    const float* xb = g_xconv + (size_t)b * HH * WW * CC;
    for (int i = tid; i < K2_PIX * 16; i += 256) {
        int pix = i >> 4;
        int c4  = i & 15;
        int row = pix / HALO_W;
        int col = pix - row * HALO_W;
        int gh = h0 + row - 1;
        int gw = w0 + col - 1;
        bool ok = ((unsigned)gh < (unsigned)HH) && ((unsigned)gw < (unsigned)WW);
        const float* src = xb + ((size_t)gh * WW + gw) * CC + c4 * 4;
        cpa16(sXS + (uint32_t)pix * (K2_PAD * 4) + c4 * 16, src, ok ? 16 : 0);
    }
    CPA_COMMIT();

    for (int i = tid; i < CC * 9; i += 256) {
        int cch = i / 9, tap = i - 9 * (i / 9);
        wd4[(((cch >> 2) * 9) + tap) * 4 + (cch & 3)] =
            __ldg(w + (size_t)cch * (CC * 9) + cch * 9 + tap);
    }
    if (tid < CC) {
        cbs[tid] = cb[tid];
        gss[tid] = gscale[tid];
        gbs[tid] = gbias[tid];
    }
    CPA_WAIT0();
    __syncthreads();

    const int lx = tid & 31;
    const int ly = tid >> 5;
    const int center = (ly + 1) * HALO_W + (lx + 1);
    const float* cp = xs + center * K2_PAD;

    float m = -1e30f;
#pragma unroll
    for (int c4 = 0; c4 < 16; c4++) {
        float4 v = *(const float4*)(cp + c4 * 4);
        m = fmaxf(m, fmaxf(fmaxf(v.x, v.y), fmaxf(v.z, v.w)));
    }
    m += 1.0f;

    float s = 0.f;
    for (int g = 0; g < GG; g++) {
        float4 c0 = *(const float4*)(cp + (g * 2 + 0) * 4);
        float4 c1 = *(const float4*)(cp + (g * 2 + 1) * 4);
        float sum = (c0.x + c0.y) + (c0.z + c0.w) + (c1.x + c1.y) + (c1.z + c1.w);
        float mean = sum * (1.0f / GS);
        float vs = 0.f;
        {
            float d;
            d = c0.x - mean; vs = fmaf(d, d, vs);
            d = c0.y - mean; vs = fmaf(d, d, vs);
            d = c0.z - mean; vs = fmaf(d, d, vs);
            d = c0.w - mean; vs = fmaf(d, d, vs);
            d = c1.x - mean; vs = fmaf(d, d, vs);
            d = c1.y - mean; vs = fmaf(d, d, vs);
            d = c1.z - mean; vs = fmaf(d, d, vs);
            d = c1.w - mean; vs = fmaf(d, d, vs);
        }
        float inv = rsqrtf(vs * (1.0f / GS) + 1e-5f);

#pragma unroll
        for (int half = 0; half < 2; half++) {
            int c4 = g * 2 + half;
            float4 acc = *(const float4*)(cbs + c4 * 4);
            const float4* wrow = (const float4*)(wd4 + c4 * 36);
#pragma unroll
            for (int t = 0; t < 9; t++) {
                int dy = t / 3, dx = t - 3 * (t / 3);
                const float4 v = *(const float4*)(xs
                    + ((ly + dy) * HALO_W + (lx + dx)) * K2_PAD + c4 * 4);
                float4 wv = wrow[t];
                acc.x = fmaf(wv.x, v.x, acc.x);
                acc.y = fmaf(wv.y, v.y, acc.y);
                acc.z = fmaf(wv.z, v.z, acc.z);
                acc.w = fmaf(wv.w, v.w, acc.w);
            }
            float4 gsv = *(const float4*)(gss + c4 * 4);
            float4 gbv = *(const float4*)(gbs + c4 * 4);
            float4 ctr = half ? c1 : c0;
#pragma unroll
            for (int k = 0; k < 4; k++) {
                float a  = (k == 0) ? acc.x : (k == 1) ? acc.y : (k == 2) ? acc.z : acc.w;
                float gsc = (k == 0) ? gsv.x : (k == 1) ? gsv.y : (k == 2) ? gsv.z : gsv.w;
                float gbc = (k == 0) ? gbv.x : (k == 1) ? gbv.y : (k == 2) ? gbv.z : gbv.w;
                float ctc = (k == 0) ? ctr.x : (k == 1) ? ctr.y : (k == 2) ? ctr.z : ctr.w;
                float norm = (a - mean) * inv * gsc + gbc;
                float gate = __saturatef(norm * (1.0f / 6.0f) + 0.5f);
                float th;
                asm("tanh.approx.f32 %0, %1;" : "=f"(th) : "f"(norm));
                float v = ctc + th * gate;
                s += __expf(v - m);
            }
        }
    }

    out[((size_t)b << 16) + (h0 + ly) * WW + (w0 + lx)] = m + __logf(s);
}

// ---------------------------------------------------------------------------
extern "C" void kernel_launch(void* const* d_in, const int* in_sizes, int n_in,
                              void* d_out, int out_size)
{
    const float* x   = (const float*)d_in[0];
    const float* w   = (const float*)d_in[1];
    const float* cb  = (const float*)d_in[2];
    const float* gsc = (const float*)d_in[3];
    const float* gbi = (const float*)d_in[4];
    float* out = (float*)d_out;

    cudaFuncSetAttribute(k1_conv,  cudaFuncAttributeMaxDynamicSharedMemorySize, SMEM1);
    cudaFuncSetAttribute(k2_fused, cudaFuncAttributeMaxDynamicSharedMemorySize, K2_SMEM_BYTES);

    k0_wconv<<<9, 256>>>(w);

    dim3 grid1(2, 128, BB);
    k1_conv<<<grid1, 256, SMEM1>>>(x, cb);

    dim3 grid2(WW / TW, HH / TH, BB);
    k2_fused<<<grid2, 256, K2_SMEM_BYTES>>>(w, cb, gsc, gbi, out);
}

// round 16
// speedup vs baseline: 1.0906x; 1.0906x over previous
#include <cuda_runtime.h>
#include <cuda_fp16.h>
#include <cstdint>

// Problem constants
#define BB 16
#define CC 64
#define HH 256
#define WW 256
#define GG 8
#define GS 8

// ---------------- k1 tiling ----------------
// A: 4 halo rows x 130 px x 128B (swizzled) = 66560 B, staged once (fp16 src)
// B: 3-tap groups (dy rows), double buffer 2 x 24576 B
#define A_ROWS (4 * 130)
#define A_BYTES (A_ROWS * 128)             // 66560
#define B_OFF A_BYTES
#define B_TAP 8192
#define B_GRP (3 * B_TAP)                  // 24576
#define SMEM1 (B_OFF + 2 * B_GRP)          // 115712 -> 2 CTAs/SM
#define EPI_PAD 68
#define K0X_SMEM (256 * EPI_PAD * 4)       // 69632

// Big device buffers (bss, not allocations)
__device__ float g_xconv[(size_t)BB * HH * WW * CC];              // [b][h][w][c]
__device__ __align__(16) __half g_xth[(size_t)BB * HH * WW * CC]; // x fp16 [b][h][w][c]
__device__ __align__(16) __half g_wsw[9][CC * CC];                // w fp16 [tap][co][ci] swizzled

__device__ __forceinline__ uint32_t smem_u32(const void* p) {
    uint32_t a;
    asm("{ .reg .u64 t; cvta.to.shared.u64 t, %1; cvt.u32.u64 %0, t; }" : "=r"(a) : "l"(p));
    return a;
}
__device__ __forceinline__ void ldsm4(uint32_t* r, uint32_t addr) {
    asm volatile("ldmatrix.sync.aligned.m8n8.x4.shared.b16 {%0,%1,%2,%3}, [%4];"
                 : "=r"(r[0]), "=r"(r[1]), "=r"(r[2]), "=r"(r[3]) : "r"(addr));
}
__device__ __forceinline__ void hmma(float* c, const uint32_t* a, const uint32_t* b) {
    asm volatile(
        "mma.sync.aligned.m16n8k16.row.col.f32.f16.f16.f32 "
        "{%0,%1,%2,%3}, {%4,%5,%6,%7}, {%8,%9}, {%0,%1,%2,%3};"
        : "+f"(c[0]), "+f"(c[1]), "+f"(c[2]), "+f"(c[3])
        : "r"(a[0]), "r"(a[1]), "r"(a[2]), "r"(a[3]), "r"(b[0]), "r"(b[1]));
}
__device__ __forceinline__ void cpa16(uint32_t dst, const void* src, int szbytes) {
    asm volatile("cp.async.ca.shared.global [%0], [%1], 16, %2;"
                 :: "r"(dst), "l"(src), "r"(szbytes) : "memory");
}
#define CPA_COMMIT() asm volatile("cp.async.commit_group;" ::: "memory")
#define CPA_WAIT0()  asm volatile("cp.async.wait_group 0;" ::: "memory")

// ---------------------------------------------------------------------------
// k0w: weights -> fp16, layout [tap][co][ci] with 16B-chunk swizzle
// ---------------------------------------------------------------------------
extern "C" __global__ void k0_wconv(const float* __restrict__ w)
{
    int tap = blockIdx.x;
    for (int i = threadIdx.x; i < CC * CC; i += 256) {
        int co = i >> 6, ci = i & 63;
        float v = w[(size_t)(co * CC + ci) * 9 + tap];
        uint32_t byte = (uint32_t)co * 128 + ((((uint32_t)ci >> 3) ^ ((uint32_t)co & 7)) << 4)
                      + ((uint32_t)ci & 7) * 2;
        g_wsw[tap][byte >> 1] = __float2half(v);
    }
}

// ---------------------------------------------------------------------------
// k0x: transpose x [b][c][h][w] f32 -> [b][h][w][c] fp16
// ---------------------------------------------------------------------------
extern "C" __global__ void __launch_bounds__(256, 1)
k0_xconv(const float* __restrict__ x)
{
    extern __shared__ uint32_t shp[];   // [256 pix][68] fp16 in low half
    const int tid = threadIdx.x;
    const int b = blockIdx.x >> 8;
    const int h = blockIdx.x & 255;
    const float* xr = x + ((size_t)b * CC * HH + h) * WW;

    for (int c = 0; c < CC; c++) {
        float v = xr[(size_t)c * HH * WW + tid];
        shp[tid * EPI_PAD + c] = (uint32_t)__half_as_ushort(__float2half(v));
    }
    __syncthreads();

    __half* oh = g_xth + (((size_t)b * HH + h) * WW) * CC;
    for (int i = tid; i < 256 * 16; i += 256) {
        int pix = i >> 4, k4 = i & 15;
        uint4 q = *(const uint4*)&shp[pix * EPI_PAD + k4 * 4];
        uint2 hv;
        hv.x = (q.x & 0xFFFFu) | (q.y << 16);
        hv.y = (q.z & 0xFFFFu) | (q.w << 16);
        *(uint2*)(oh + (size_t)pix * CC + k4 * 4) = hv;
    }
}

// ---------------------------------------------------------------------------
// k1: conv3x3 + bias via mma.sync fp16, out [b][h][w][c]
//   3 passes of 3 taps (one dy-row each); B group-staged double-buffered.
//   grid (2, 128, 16); 256 threads; 2 CTAs/SM
// ---------------------------------------------------------------------------
extern "C" __global__ void __launch_bounds__(256, 2)
k1_conv(const float* __restrict__ cb)
{
    extern __shared__ char smem[];
    const uint32_t sA = smem_u32(smem);
    const int tid = threadIdx.x;
    const int wid = tid >> 5;
    const int lid = tid & 31;

    const int b  = blockIdx.z;
    const int h0 = blockIdx.y * 2;
    const int w0 = blockIdx.x * 128;

    const int am  = lid & 15;
    const int akh = (lid >> 4) & 1;
    const int bco = (lid & 7) + ((lid >= 16) ? 8 : 0);
    const int bkh = (lid >> 3) & 1;
    const int pbase = wid * 16;

    // ---- stage A (once) ----
    for (int i = tid; i < A_ROWS * 8; i += 256) {
        int rs = i >> 3, chunk = i & 7;
        int R  = rs / 130;
        int px = rs - R * 130;
        int gh = h0 - 1 + R;
        int gw = w0 - 1 + px;
        bool ok = ((unsigned)gh < (unsigned)HH) && ((unsigned)gw < (unsigned)WW);
        const __half* src = g_xth + ((((size_t)b * HH + gh) * WW + gw) * CC) + chunk * 8;
        uint32_t dst = sA + rs * 128 + ((chunk ^ (rs & 7)) << 4);
        cpa16(dst, src, ok ? 16 : 0);
    }
    // stage one 3-tap group (taps 3*grp .. 3*grp+2, contiguous in g_wsw)
    auto stageB3 = [&](int buf, int grp) {
        uint32_t dst = sA + B_OFF + buf * B_GRP;
        const char* s0 = (const char*)&g_wsw[grp * 3][0];
        for (int i = tid; i < B_GRP / 16; i += 256)
            cpa16(dst + i * 16, s0 + i * 16, 16);
    };

    float c[2][8][4];
#pragma unroll
    for (int hh = 0; hh < 2; hh++)
#pragma unroll
        for (int nb = 0; nb < 8; nb++)
#pragma unroll
            for (int q = 0; q < 4; q++) c[hh][nb][q] = 0.f;

    stageB3(0, 0);
    CPA_COMMIT();

    int cur = 0;
    for (int grp = 0; grp < 3; grp++) {
        CPA_WAIT0();
        __syncthreads();

        if (grp < 2) {
            stageB3(cur ^ 1, grp + 1);
            CPA_COMMIT();
        }

        const int dy = grp;
#pragma unroll
        for (int dx = 0; dx < 3; dx++) {
            const uint32_t sBc = sA + B_OFF + cur * B_GRP + dx * B_TAP + bco * 128;
#pragma unroll
            for (int kb = 0; kb < 4; kb++) {
                uint32_t a[2][4];
#pragma unroll
                for (int hh = 0; hh < 2; hh++) {
                    int rs = (hh + dy) * 130 + pbase + dx + am;
                    uint32_t addr = sA + rs * 128
                                  + ((((uint32_t)(kb * 2 + akh)) ^ (rs & 7)) << 4);
                    ldsm4(a[hh], addr);
                }
                uint32_t bbf[4][4];
#pragma unroll
                for (int j = 0; j < 4; j++) {
                    uint32_t co = (uint32_t)(j * 16 + bco);
                    uint32_t addr = sBc + j * 16 * 128
                                  + ((((uint32_t)(kb * 2 + bkh)) ^ (co & 7)) << 4);
                    ldsm4(bbf[j], addr);
                }
#pragma unroll
                for (int hh = 0; hh < 2; hh++)
#pragma unroll
                    for (int j = 0; j < 4; j++) {
                        hmma(c[hh][2 * j + 0], a[hh], &bbf[j][0]);
                        hmma(c[hh][2 * j + 1], a[hh], &bbf[j][2]);
                    }
            }
        }
        cur ^= 1;
    }

    // ---- epilogue: frags -> smem [256 px][68] f32 -> coalesced gmem ----
    __syncthreads();
    float* smf = (float*)smem;
    const int mrow = (lid >> 2);
    const int qcol = (lid & 3) * 2;
#pragma unroll
    for (int hh = 0; hh < 2; hh++)
#pragma unroll
        for (int nb = 0; nb < 8; nb++) {
            int m0 = hh * 128 + pbase + mrow;
            int co = nb * 8 + qcol;
            *(float2*)&smf[m0 * EPI_PAD + co]       = make_float2(c[hh][nb][0], c[hh][nb][1]);
            *(float2*)&smf[(m0 + 8) * EPI_PAD + co] = make_float2(c[hh][nb][2], c[hh][nb][3]);
        }
    __syncthreads();

    for (int i = tid; i < 256 * 16; i += 256) {
        int pix = i >> 4, k4 = i & 15;
        float4 v = *(float4*)&smf[pix * EPI_PAD + k4 * 4];
        int cc4 = k4 * 4;
        v.x += __ldg(cb + cc4 + 0);
        v.y += __ldg(cb + cc4 + 1);
        v.z += __ldg(cb + cc4 + 2);
        v.w += __ldg(cb + cc4 + 3);
        int gh = h0 + (pix >> 7);
        int gw = w0 + (pix & 127);
        *(float4*)(g_xconv + (((size_t)b * HH + gh) * WW + gw) * CC + cc4) = v;
    }
}

// ---------------------------------------------------------------------------
// k2: fused epilogue, channels-last smem tile [pix][68] (unchanged R14)
// ---------------------------------------------------------------------------
#define TW 32
#define TH 8
#define HALO_W (TW + 2)
#define HALO_H (TH + 2)
#define K2_PIX (HALO_W * HALO_H)           // 340
#define K2_PAD 68
#define K2_XS_FLOATS (K2_PIX * K2_PAD)
#define K2_WD_OFF K2_XS_FLOATS
#define K2_CB_OFF (K2_WD_OFF + 576)
#define K2_GS_OFF (K2_CB_OFF + CC)
#define K2_GB_OFF (K2_GS_OFF + CC)
#define K2_SMEM_FLOATS (K2_GB_OFF + CC)
#define K2_SMEM_BYTES (K2_SMEM_FLOATS * 4)

extern "C" __global__ void __launch_bounds__(256, 2)
k2_fused(const float* __restrict__ w,
         const float* __restrict__ cb,
         const float* __restrict__ gscale,
         const float* __restrict__ gbias,
         float* __restrict__ out)
{
    extern __shared__ float smemf[];
    float* xs  = smemf;
    float* wd4 = smemf + K2_WD_OFF;
    float* cbs = smemf + K2_CB_OFF;
    float* gss = smemf + K2_GS_OFF;
    float* gbs = smemf + K2_GB_OFF;

    const uint32_t sXS = smem_u32(xs);
    const int tid = threadIdx.x;
    const int b  = blockIdx.z;
    const int h0 = blockIdx.y * TH;
    const int w0 = blockIdx.x * TW;

    const float* xb = g_xconv + (size_t)b * HH * WW * CC;
    for (int i = tid; i < K2_PIX * 16; i += 256) {
        int pix = i >> 4;
        int c4  = i & 15;
        int row = pix / HALO_W;
        int col = pix - row * HALO_W;
        int gh = h0 + row - 1;
        int gw = w0 + col - 1;
        bool ok = ((unsigned)gh < (unsigned)HH) && ((unsigned)gw < (unsigned)WW);
        const float* src = xb + ((size_t)gh * WW + gw) * CC + c4 * 4;
        cpa16(sXS + (uint32_t)pix * (K2_PAD * 4) + c4 * 16, src, ok ? 16 : 0);
    }
    CPA_COMMIT();

    for (int i = tid; i < CC * 9; i += 256) {
        int cch = i / 9, tap = i - 9 * (i / 9);
        wd4[(((cch >> 2) * 9) + tap) * 4 + (cch & 3)] =
            __ldg(w + (size_t)cch * (CC * 9) + cch * 9 + tap);
    }
    if (tid < CC) {
        cbs[tid] = cb[tid];
        gss[tid] = gscale[tid];
        gbs[tid] = gbias[tid];
    }
    CPA_WAIT0();
    __syncthreads();

    const int lx = tid & 31;
    const int ly = tid >> 5;
    const int center = (ly + 1) * HALO_W + (lx + 1);
    const float* cp = xs + center * K2_PAD;

    float m = -1e30f;
#pragma unroll
    for (int c4 = 0; c4 < 16; c4++) {
        float4 v = *(const float4*)(cp + c4 * 4);
        m = fmaxf(m, fmaxf(fmaxf(v.x, v.y), fmaxf(v.z, v.w)));
    }
    m += 1.0f;

    float s = 0.f;
    for (int g = 0; g < GG; g++) {
        float4 c0 = *(const float4*)(cp + (g * 2 + 0) * 4);
        float4 c1 = *(const float4*)(cp + (g * 2 + 1) * 4);
        float sum = (c0.x + c0.y) + (c0.z + c0.w) + (c1.x + c1.y) + (c1.z + c1.w);
        float mean = sum * (1.0f / GS);
        float vs = 0.f;
        {
            float d;
            d = c0.x - mean; vs = fmaf(d, d, vs);
            d = c0.y - mean; vs = fmaf(d, d, vs);
            d = c0.z - mean; vs = fmaf(d, d, vs);
            d = c0.w - mean; vs = fmaf(d, d, vs);
            d = c1.x - mean; vs = fmaf(d, d, vs);
            d = c1.y - mean; vs = fmaf(d, d, vs);
            d = c1.z - mean; vs = fmaf(d, d, vs);
            d = c1.w - mean; vs = fmaf(d, d, vs);
        }
        float inv = rsqrtf(vs * (1.0f / GS) + 1e-5f);

#pragma unroll
        for (int half = 0; half < 2; half++) {
            int c4 = g * 2 + half;
            float4 acc = *(const float4*)(cbs + c4 * 4);
            const float4* wrow = (const float4*)(wd4 + c4 * 36);
#pragma unroll
            for (int t = 0; t < 9; t++) {
                int dy = t / 3, dx = t - 3 * (t / 3);
                const float4 v = *(const float4*)(xs
                    + ((ly + dy) * HALO_W + (lx + dx)) * K2_PAD + c4 * 4);
                float4 wv = wrow[t];
                acc.x = fmaf(wv.x, v.x, acc.x);
                acc.y = fmaf(wv.y, v.y, acc.y);
                acc.z = fmaf(wv.z, v.z, acc.z);
                acc.w = fmaf(wv.w, v.w, acc.w);
            }
            float4 gsv = *(const float4*)(gss + c4 * 4);
            float4 gbv = *(const float4*)(gbs + c4 * 4);
            float4 ctr = half ? c1 : c0;
#pragma unroll
            for (int k = 0; k < 4; k++) {
                float a  = (k == 0) ? acc.x : (k == 1) ? acc.y : (k == 2) ? acc.z : acc.w;
                float gsc = (k == 0) ? gsv.x : (k == 1) ? gsv.y : (k == 2) ? gsv.z : gsv.w;
                float gbc = (k == 0) ? gbv.x : (k == 1) ? gbv.y : (k == 2) ? gbv.z : gbv.w;
                float ctc = (k == 0) ? ctr.x : (k == 1) ? ctr.y : (k == 2) ? ctr.z : ctr.w;
                float norm = (a - mean) * inv * gsc + gbc;
                float gate = __saturatef(norm * (1.0f / 6.0f) + 0.5f);
                float th;
                asm("tanh.approx.f32 %0, %1;" : "=f"(th) : "f"(norm));
                float v = ctc + th * gate;
                s += __expf(v - m);
            }
        }
    }

    out[((size_t)b << 16) + (h0 + ly) * WW + (w0 + lx)] = m + __logf(s);
}

// ---------------------------------------------------------------------------
extern "C" void kernel_launch(void* const* d_in, const int* in_sizes, int n_in,
                              void* d_out, int out_size)
{
    const float* x   = (const float*)d_in[0];
    const float* w   = (const float*)d_in[1];
    const float* cb  = (const float*)d_in[2];
    const float* gsc = (const float*)d_in[3];
    const float* gbi = (const float*)d_in[4];
    float* out = (float*)d_out;

    cudaFuncSetAttribute(k0_xconv, cudaFuncAttributeMaxDynamicSharedMemorySize, K0X_SMEM);
    cudaFuncSetAttribute(k1_conv,  cudaFuncAttributeMaxDynamicSharedMemorySize, SMEM1);
    cudaFuncSetAttribute(k2_fused, cudaFuncAttributeMaxDynamicSharedMemorySize, K2_SMEM_BYTES);

    k0_wconv<<<9, 256>>>(w);
    k0_xconv<<<BB * HH, 256, K0X_SMEM>>>(x);

    dim3 grid1(2, 128, BB);
    k1_conv<<<grid1, 256, SMEM1>>>(cb);

    dim3 grid2(WW / TW, HH / TH, BB);
    k2_fused<<<grid2, 256, K2_SMEM_BYTES>>>(w, cb, gsc, gbi, out);
}